// round 13
// baseline (speedup 1.0000x reference)
#include <cuda_runtime.h>
#include <cuda_fp16.h>
#include <cstdint>
#include <cstddef>

#define NBATCH 32
#define NNODE  512
#define NTIME  12
#define NCH    64
#define NM     (NTIME * NCH)            /* 768 */
#define NROWS  (NBATCH * NNODE * NTIME) /* 196608 */
#define ZELEMS ((size_t)NBATCH * NM * NNODE) /* 12582912 */
#define NN     ((size_t)NNODE * NNODE)

/* ------------------------------------------------------------------ */
/* Device scratch                                                      */
/* ------------------------------------------------------------------ */
__device__ float g_SW1[40 * 20];
__device__ float g_SW2[40 * 20];
__device__ float g_e1[NNODE * 20];
__device__ float g_e2[NNODE * 20];
__device__ float g_A[NNODE * NNODE];
__device__ float g_dinv[NNODE];
__device__ float g_Ls[NNODE * NNODE];
__device__ float g_T2[NNODE * NNODE];
__device__ float g_T3[NNODE * NNODE];
__device__ float g_P2[3][NNODE * NNODE];  /* S_s^2, fp32 */
__device__ float g_P3[3][NNODE * NNODE];  /* S_s^3, fp32 */
__device__ float g_Wid[64 * 64];

/* 9 transposed operators in fp16: op = s*3 + (p-1) */
__device__ __align__(1024) __half g_OPT[9][NNODE * NNODE];
__device__ __align__(1024) __half g_Zx[ZELEMS];
__device__ __align__(1024) __half g_Zall[9 * ZELEMS];

/* ------------------------------------------------------------------ */
/* PTX helpers (plain compute_100-legal)                               */
/* ------------------------------------------------------------------ */
__device__ __forceinline__ uint32_t smem_to_u32(const void* p) {
    uint32_t a;
    asm("{ .reg .u64 t; cvta.to.shared.u64 t, %1; cvt.u32.u64 %0, t; }"
        : "=r"(a) : "l"(p));
    return a;
}
__device__ __forceinline__ void cpasync16(uint32_t s, const void* g) {
    asm volatile("cp.async.cg.shared.global [%0], [%1], 16;" :: "r"(s), "l"(g));
}
#define CP_COMMIT() asm volatile("cp.async.commit_group;" ::: "memory")
#define CP_WAIT1()  asm volatile("cp.async.wait_group 1;" ::: "memory")
#define CP_WAIT0()  asm volatile("cp.async.wait_group 0;" ::: "memory")

__device__ __forceinline__ void ldsm4(uint32_t& r0, uint32_t& r1,
                                      uint32_t& r2, uint32_t& r3, uint32_t a) {
    asm volatile("ldmatrix.sync.aligned.m8n8.x4.shared.b16 {%0,%1,%2,%3}, [%4];"
                 : "=r"(r0), "=r"(r1), "=r"(r2), "=r"(r3) : "r"(a));
}
__device__ __forceinline__ void mma16816f(float* c, const uint32_t* a,
                                          const uint32_t* b) {
    asm volatile(
        "mma.sync.aligned.m16n8k16.row.col.f32.f16.f16.f32 "
        "{%0,%1,%2,%3}, {%4,%5,%6,%7}, {%8,%9}, {%0,%1,%2,%3};"
        : "+f"(c[0]), "+f"(c[1]), "+f"(c[2]), "+f"(c[3])
        : "r"(a[0]), "r"(a[1]), "r"(a[2]), "r"(a[3]), "r"(b[0]), "r"(b[1]));
}

/* ------------------------------------------------------------------ */
/* Phase A (tiny)                                                      */
/* ------------------------------------------------------------------ */
__global__ void k_softmax(const float* __restrict__ W1,
                          const float* __restrict__ W2) {
    int j = threadIdx.x;
    if (j >= 40) return;
    const float* W = (j < 20) ? W1 : W2;
    float* S = (j < 20) ? g_SW1 : g_SW2;
    int col = (j < 20) ? j : (j - 20);
    float mx = -1e30f;
    for (int k = 0; k < 40; k++) mx = fmaxf(mx, W[k * 20 + col]);
    float s = 0.f;
    for (int k = 0; k < 40; k++) s += expf(W[k * 20 + col] - mx);
    float inv = 1.f / s;
    for (int k = 0; k < 40; k++) S[k * 20 + col] = expf(W[k * 20 + col] - mx) * inv;
}

__global__ void k_embed(const float* __restrict__ emb) {
    int row = blockIdx.x;
    int lane = threadIdx.x;
    float v1 = 0.f, v2 = 0.f;
    if (lane < 20) {
        for (int k = 0; k < 40; k++) {
            float e = emb[row * 40 + k];
            v1 += e * g_SW1[k * 20 + lane];
            v2 += e * g_SW2[k * 20 + lane];
        }
    }
    float n1 = v1 * v1, n2 = v2 * v2;
    for (int off = 16; off; off >>= 1) {
        n1 += __shfl_xor_sync(0xFFFFFFFFu, n1, off);
        n2 += __shfl_xor_sync(0xFFFFFFFFu, n2, off);
    }
    if (lane < 20) {
        g_e1[row * 20 + lane] = v1 / (sqrtf(n1) + 1e-8f);
        g_e2[row * 20 + lane] = v2 / (sqrtf(n2) + 1e-8f);
    }
}

__global__ void k_buildA(const float* __restrict__ adj) {
    int v = blockIdx.x;
    __shared__ float e1v[20];
    __shared__ float red[256];
    if (threadIdx.x < 20) e1v[threadIdx.x] = g_e1[v * 20 + threadIdx.x];
    __syncthreads();
    float sum = 0.f;
    for (int w = threadIdx.x; w < NNODE; w += 256) {
        float ad = adj[v * NNODE + w];
        float val = 9e-15f;
        if (ad > 0.f) {
            float dot = 0.f;
#pragma unroll
            for (int k = 0; k < 20; k++) dot += e1v[k] * g_e2[w * 20 + k];
            val = dot + ad;
        }
        g_A[v * NNODE + w] = val;
        sum += val;
    }
    red[threadIdx.x] = sum;
    __syncthreads();
    for (int s = 128; s; s >>= 1) {
        if (threadIdx.x < s) red[threadIdx.x] += red[threadIdx.x + s];
        __syncthreads();
    }
    if (threadIdx.x == 0) g_dinv[v] = 1.0f / sqrtf(red[0]);
}

__global__ void k_Ls() {
    int v = blockIdx.x;
    float dv = g_dinv[v];
    for (int w = threadIdx.x; w < NNODE; w += 256)
        g_Ls[v * NNODE + w] = -dv * g_A[v * NNODE + w] * g_dinv[w];
}

/* C = 2*A@B - (D ? D : I), 512x512 fp32 */
__global__ void k_gemm512(const float* __restrict__ A,
                          const float* __restrict__ B,
                          const float* __restrict__ D,
                          float* __restrict__ C) {
    __shared__ float As[16][68];
    __shared__ float Bs[16][68];
    const int tx = threadIdx.x, ty = threadIdx.y;
    const int t = ty * 16 + tx;
    const int i0 = blockIdx.y * 64, j0 = blockIdx.x * 64;
    float acc[4][4] = {};
    for (int k0 = 0; k0 < NNODE; k0 += 16) {
#pragma unroll
        for (int r = 0; r < 4; r++) {
            int idx = t + r * 256;
            int ia = idx >> 4, ka = idx & 15;
            As[ka][ia] = A[(size_t)(i0 + ia) * NNODE + k0 + ka];
            int kb = idx >> 6, jb = idx & 63;
            Bs[kb][jb] = B[(size_t)(k0 + kb) * NNODE + j0 + jb];
        }
        __syncthreads();
#pragma unroll
        for (int k = 0; k < 16; k++) {
            float av[4], bv[4];
#pragma unroll
            for (int i = 0; i < 4; i++) av[i] = As[k][ty * 4 + i];
#pragma unroll
            for (int j = 0; j < 4; j++) bv[j] = Bs[k][tx * 4 + j];
#pragma unroll
            for (int i = 0; i < 4; i++)
#pragma unroll
                for (int j = 0; j < 4; j++) acc[i][j] = fmaf(av[i], bv[j], acc[i][j]);
        }
        __syncthreads();
    }
#pragma unroll
    for (int i = 0; i < 4; i++)
#pragma unroll
        for (int j = 0; j < 4; j++) {
            int gi = i0 + ty * 4 + i, gj = j0 + tx * 4 + j;
            float sub = D ? D[(size_t)gi * NNODE + gj] : (gi == gj ? 1.f : 0.f);
            C[(size_t)gi * NNODE + gj] = 2.f * acc[i][j] - sub;
        }
}

/* Plain power GEMM, batched over 3 chains: mode 0: P2[s]=S_s@S_s,
   mode 1: P3[s]=S_s@P2[s]. */
__global__ void k_gemm512p(int mode, float* __restrict__ P2b,
                           float* __restrict__ P3b) {
    __shared__ float As[16][68];
    __shared__ float Bs[16][68];
    const int s = blockIdx.z;
    const float* S = (s == 0) ? g_Ls : (s == 1) ? g_T2 : g_T3;
    const float* A = S;
    const float* B = (mode == 0) ? S : (P2b + (size_t)s * NN);
    float* C = (mode == 0) ? (P2b + (size_t)s * NN) : (P3b + (size_t)s * NN);
    const int tx = threadIdx.x, ty = threadIdx.y;
    const int t = ty * 16 + tx;
    const int i0 = blockIdx.y * 64, j0 = blockIdx.x * 64;
    float acc[4][4] = {};
    for (int k0 = 0; k0 < NNODE; k0 += 16) {
#pragma unroll
        for (int r = 0; r < 4; r++) {
            int idx = t + r * 256;
            int ia = idx >> 4, ka = idx & 15;
            As[ka][ia] = A[(size_t)(i0 + ia) * NNODE + k0 + ka];
            int kb = idx >> 6, jb = idx & 63;
            Bs[kb][jb] = B[(size_t)(k0 + kb) * NNODE + j0 + jb];
        }
        __syncthreads();
#pragma unroll
        for (int k = 0; k < 16; k++) {
            float av[4], bv[4];
#pragma unroll
            for (int i = 0; i < 4; i++) av[i] = As[k][ty * 4 + i];
#pragma unroll
            for (int j = 0; j < 4; j++) bv[j] = Bs[k][tx * 4 + j];
#pragma unroll
            for (int i = 0; i < 4; i++)
#pragma unroll
                for (int j = 0; j < 4; j++) acc[i][j] = fmaf(av[i], bv[j], acc[i][j]);
        }
        __syncthreads();
    }
#pragma unroll
    for (int i = 0; i < 4; i++)
#pragma unroll
        for (int j = 0; j < 4; j++)
            C[(size_t)(i0 + ty * 4 + i) * NNODE + j0 + tx * 4 + j] = acc[i][j];
}

__global__ void k_wid(const float* __restrict__ mlpw) {
    int i = blockIdx.x * 256 + threadIdx.x;
    int o = i >> 6, c = i & 63;
    g_Wid[i] = mlpw[o * 832 + c] + mlpw[o * 832 + 64 + c] +
               mlpw[o * 832 + 128 + c] + mlpw[o * 832 + 192 + c];
}

/* OPT[op][w][v] = (A_s^p)[v][w] fp16, op = s*3 + (p-1) */
__global__ void k_att9() {
    __shared__ float tile[32][33];
    const int op = blockIdx.z;
    const int s = op / 3, p = op % 3; /* p: 0->S, 1->S^2, 2->S^3 */
    const float* S;
    if (p == 0) S = (s == 0) ? g_Ls : (s == 1) ? g_T2 : g_T3;
    else if (p == 1) S = g_P2[s];
    else S = g_P3[s];
    __half* T = g_OPT[op];
    int w0 = blockIdx.x * 32, v0 = blockIdx.y * 32;
    int tx = threadIdx.x, ty = threadIdx.y;
#pragma unroll
    for (int i = 0; i < 4; i++)
        tile[ty + i * 8][tx] = S[(size_t)(v0 + ty + i * 8) * NNODE + w0 + tx];
    __syncthreads();
#pragma unroll
    for (int i = 0; i < 4; i++) {
        size_t idx = (size_t)(w0 + ty + i * 8) * NNODE + v0 + tx;
        T[idx] = __float2half(tile[tx][ty + i * 8]);
    }
}

/* Zx[b][m][v] = x[b][v][m], single fp16 */
__global__ void k_xpose(const float* __restrict__ x,
                        __half* __restrict__ Z) {
    __shared__ float tile[32][33];
    int m0 = blockIdx.x * 32, v0 = blockIdx.y * 32, b = blockIdx.z;
    int tx = threadIdx.x, ty = threadIdx.y;
#pragma unroll
    for (int i = 0; i < 4; i++)
        tile[ty + i * 8][tx] = x[((size_t)b * NNODE + v0 + ty + i * 8) * NM + m0 + tx];
    __syncthreads();
#pragma unroll
    for (int i = 0; i < 4; i++) {
        float val = tile[tx][ty + i * 8];
        size_t idx = ((size_t)b * NM + m0 + ty + i * 8) * NNODE + v0 + tx;
        Z[idx] = __float2half(val);
    }
}

/* ------------------------------------------------------------------ */
/* HMMA node GEMM (fp16): Zall[op] = Zx * OPT[op]                      */
/* Block 128m x 256n, 8 warps (2m x 4n) of 64x64, BK=16                */
/* 3-stage cp.async ring, one __syncthreads per iteration              */
/* blockIdx.z = op*32 + b, all 9 operators in ONE launch               */
/* ------------------------------------------------------------------ */
#define BKQ 16
#define ROWB 48                       /* 16 fp16 = 32 B data + 16 pad   */
#define ZT_BYTES (128 * ROWB)         /* 6144  */
#define BT_BYTES (256 * ROWB)         /* 12288 */
#define STAGE_BYTES (ZT_BYTES + BT_BYTES) /* 18432 */
#define NSTAGE 3
#define GEMM_SMEM (NSTAGE * STAGE_BYTES)  /* 55296 -> opt-in attribute  */

__global__ void __launch_bounds__(256, 1) k_node_gemm_mma(
    const __half* __restrict__ Zx, const __half* __restrict__ OPTb,
    __half* __restrict__ Zallb) {
    extern __shared__ __align__(128) char smem[];
    const uint32_t sb = smem_to_u32(smem);
    const int tid = threadIdx.x, wid = tid >> 5, lane = tid & 31;
    const int m0 = blockIdx.x * 128;
    const int w0 = blockIdx.y * 256;
    const int op = blockIdx.z >> 5;
    const int b = blockIdx.z & 31;
    const __half* AT = OPTb + (size_t)op * NN;
    __half* Zout = Zallb + (size_t)op * ZELEMS;
    const size_t zbase = ((size_t)b * NM + m0) * NNODE;
    const int warp_m = wid & 1;   /* 64-row half   */
    const int warp_n = wid >> 1;  /* 64-col strip  */

    float acc[4][8][4];
#pragma unroll
    for (int i = 0; i < 4; i++)
#pragma unroll
        for (int j = 0; j < 8; j++)
#pragma unroll
            for (int k = 0; k < 4; k++) acc[i][j][k] = 0.f;

    /* stage loader: 768 cp.async of 16B = 3 per thread                 */
    auto load_stage = [&](int it, int s) {
        const int k0 = it * BKQ;
        const uint32_t sbase = sb + s * STAGE_BYTES;
#pragma unroll
        for (int i = 0; i < 3; i++) {
            int c = tid + i * 256;           /* 0..767 */
            if (c < 256) {                   /* Z tile: 128 rows x 2 halves */
                int row = c >> 1, h = c & 1;
                cpasync16(sbase + row * ROWB + h * 16,
                          Zx + zbase + (size_t)row * NNODE + k0 + h * 8);
            } else {                         /* B tile: 256 rows x 2 halves */
                int cm = c - 256;
                int row = cm >> 1, h = cm & 1;
                cpasync16(sbase + ZT_BYTES + row * ROWB + h * 16,
                          AT + (size_t)(w0 + row) * NNODE + k0 + h * 8);
            }
        }
    };

    load_stage(0, 0);
    CP_COMMIT();
    load_stage(1, 1);
    CP_COMMIT();

    const uint32_t lrow = lane & 15;
    const uint32_t lhalf = (uint32_t)(lane >> 4) * 16;
    const int NIT = NNODE / BKQ; /* 32 */

    for (int it = 0; it < NIT; it++) {
        if (it < NIT - 1) CP_WAIT1(); else CP_WAIT0();
        __syncthreads();
        if (it + 2 < NIT) {
            load_stage(it + 2, (it + 2) % NSTAGE);
            CP_COMMIT();
        }

        const uint32_t sbase = sb + (it % NSTAGE) * STAGE_BYTES;
        uint32_t z[4][4], bq[8][2];
#pragma unroll
        for (int mt = 0; mt < 4; mt++) {
            uint32_t a = sbase + (warp_m * 64 + mt * 16 + lrow) * ROWB + lhalf;
            ldsm4(z[mt][0], z[mt][1], z[mt][2], z[mt][3], a);
        }
#pragma unroll
        for (int nq = 0; nq < 4; nq++) {
            uint32_t a = sbase + ZT_BYTES +
                         (warp_n * 64 + nq * 16 + lrow) * ROWB + lhalf;
            uint32_t r0, r1, r2, r3;
            ldsm4(r0, r1, r2, r3, a);
            bq[nq * 2][0] = r0; bq[nq * 2][1] = r2;
            bq[nq * 2 + 1][0] = r1; bq[nq * 2 + 1][1] = r3;
        }
#pragma unroll
        for (int mt = 0; mt < 4; mt++)
#pragma unroll
            for (int nt = 0; nt < 8; nt++)
                mma16816f(acc[mt][nt], z[mt], bq[nt]);
    }

    /* epilogue: single fp16 output */
    const int qr = lane >> 2;
    const int qc = (lane & 3) * 2;
#pragma unroll
    for (int mt = 0; mt < 4; mt++) {
#pragma unroll
        for (int nt = 0; nt < 8; nt++) {
            const int row0 = m0 + warp_m * 64 + mt * 16 + qr;
            const int col = w0 + warp_n * 64 + nt * 8 + qc;
            const float* c = acc[mt][nt];
            size_t i0 = ((size_t)b * NM + row0) * NNODE + col;
            size_t i1 = i0 + (size_t)8 * NNODE;
            *(__half2*)(Zout + i0) = __floats2half2_rn(c[0], c[1]);
            *(__half2*)(Zout + i1) = __floats2half2_rn(c[2], c[3]);
        }
    }
}

/* ------------------------------------------------------------------ */
/* Unified epilogue: identity (fp32 x) + 9 blocks (fp16 Z) +           */
/* bias + residual + relu, single out write                            */
/* ------------------------------------------------------------------ */
__global__ void __launch_bounds__(256) k_epilogue(
    const float* __restrict__ x, const __half* __restrict__ Zall,
    const float* __restrict__ mlpw, const float* __restrict__ bias,
    float* __restrict__ out) {
    __shared__ float Ws[64][65];
    __shared__ float Ys[64][65];
    const int wblk = blockIdx.x;
    const int t = blockIdx.y;
    const int b = blockIdx.z;
    const int tid = threadIdx.x, tx = tid & 15, ty = tid >> 4;
    float acc[4][4] = {};

    /* pass 0: identity block from fp32 x (exact) with g_Wid */
    {
        for (int i = tid; i < 4096; i += 256) {
            int o = i >> 6, c = i & 63;
            Ws[c][o] = g_Wid[o * 64 + c];
        }
        for (int i = tid; i < 4096; i += 256) {
            int wp = i >> 6, c = i & 63;
            Ys[c][wp] = x[((size_t)(b * NNODE + wblk * 64 + wp) * NTIME + t) * 64 + c];
        }
        __syncthreads();
#pragma unroll
        for (int c = 0; c < 64; c++) {
            float yv[4], wv[4];
#pragma unroll
            for (int i = 0; i < 4; i++) yv[i] = Ys[c][ty * 4 + i];
#pragma unroll
            for (int j = 0; j < 4; j++) wv[j] = Ws[c][tx * 4 + j];
#pragma unroll
            for (int i = 0; i < 4; i++)
#pragma unroll
                for (int j = 0; j < 4; j++) acc[i][j] = fmaf(yv[i], wv[j], acc[i][j]);
        }
        __syncthreads();
    }

    /* passes: 9 blocks; zi = s*3 + (p-1) -> mlp block 4 + 3s + (p-1)   */
#pragma unroll 1
    for (int zi = 0; zi < 9; zi++) {
        const int s = zi / 3, hop = zi % 3;
        const int coloff = (4 + 3 * s + hop) * 64;
        const __half* Z = Zall + (size_t)zi * ZELEMS;
        for (int i = tid; i < 4096; i += 256) {
            int o = i >> 6, c = i & 63;
            Ws[c][o] = mlpw[(size_t)o * 832 + coloff + c];
        }
        for (int i = tid; i < 2048; i += 256) {
            int c = i >> 5, p = i & 31;
            size_t idx = ((size_t)b * NM + t * 64 + c) * NNODE + wblk * 64 + p * 2;
            __half2 v = *(const __half2*)(Z + idx);
            float2 f = __half22float2(v);
            Ys[c][p * 2] = f.x;
            Ys[c][p * 2 + 1] = f.y;
        }
        __syncthreads();
#pragma unroll
        for (int c = 0; c < 64; c++) {
            float yv[4], wv[4];
#pragma unroll
            for (int i = 0; i < 4; i++) yv[i] = Ys[c][ty * 4 + i];
#pragma unroll
            for (int j = 0; j < 4; j++) wv[j] = Ws[c][tx * 4 + j];
#pragma unroll
            for (int i = 0; i < 4; i++)
#pragma unroll
                for (int j = 0; j < 4; j++) acc[i][j] = fmaf(yv[i], wv[j], acc[i][j]);
        }
        __syncthreads();
    }

    /* write: bias + residual + relu, no RMW */
#pragma unroll
    for (int i = 0; i < 4; i++) {
        size_t r = ((size_t)(b * NNODE + wblk * 64 + ty * 4 + i) * NTIME + t);
        float* po = out + r * 64 + tx * 4;
        const float4 bb = *(const float4*)(bias + tx * 4);
        const float4 xo = *(const float4*)(x + r * 64 + tx * 4);
        float4 v;
        v.x = fmaxf(acc[i][0] + bb.x + xo.x, 0.f);
        v.y = fmaxf(acc[i][1] + bb.y + xo.y, 0.f);
        v.z = fmaxf(acc[i][2] + bb.z + xo.z, 0.f);
        v.w = fmaxf(acc[i][3] + bb.w + xo.w, 0.f);
        *(float4*)po = v;
    }
}

/* ------------------------------------------------------------------ */
extern "C" void kernel_launch(void* const* d_in, const int* in_sizes, int n_in,
                              void* d_out, int out_size) {
    (void)in_sizes; (void)n_in; (void)out_size;
    const float* x    = (const float*)d_in[0];
    const float* adj  = (const float*)d_in[1];
    const float* emb  = (const float*)d_in[2];
    const float* W1   = (const float*)d_in[3];
    const float* W2   = (const float*)d_in[4];
    const float* mlpw = (const float*)d_in[5];
    const float* mlpb = (const float*)d_in[6];
    float* out = (float*)d_out;

    float *pLs, *pT2, *pT3, *pP2, *pP3;
    __half *pOPT, *pZx, *pZall;
    cudaGetSymbolAddress((void**)&pLs, g_Ls);
    cudaGetSymbolAddress((void**)&pT2, g_T2);
    cudaGetSymbolAddress((void**)&pT3, g_T3);
    cudaGetSymbolAddress((void**)&pP2, g_P2);
    cudaGetSymbolAddress((void**)&pP3, g_P3);
    cudaGetSymbolAddress((void**)&pOPT, g_OPT);
    cudaGetSymbolAddress((void**)&pZx, g_Zx);
    cudaGetSymbolAddress((void**)&pZall, g_Zall);

    cudaFuncSetAttribute(k_node_gemm_mma,
                         cudaFuncAttributeMaxDynamicSharedMemorySize, GEMM_SMEM);

    /* Phase A: supports + powers */
    k_softmax<<<1, 64>>>(W1, W2);
    k_embed<<<512, 32>>>(emb);
    k_buildA<<<512, 256>>>(adj);
    k_Ls<<<512, 256>>>();
    dim3 g512(8, 8), b512(16, 16);
    k_gemm512<<<g512, b512>>>(pLs, pLs, (const float*)nullptr, pT2);
    k_gemm512<<<g512, b512>>>(pLs, pT2, pLs, pT3);
    dim3 gp(8, 8, 3);
    k_gemm512p<<<gp, b512>>>(0, pP2, pP3);  /* P2[s] = S_s^2 */
    k_gemm512p<<<gp, b512>>>(1, pP2, pP3);  /* P3[s] = S_s^3 */
    dim3 ga9(16, 16, 9), bat(32, 8);
    k_att9<<<ga9, bat>>>();
    k_wid<<<16, 256>>>(mlpw);

    /* transpose x -> Zx (fp16, rounded ONCE) */
    dim3 gx(24, 16, 32), bx(32, 8);
    k_xpose<<<gx, bx>>>(x, pZx);

    /* all 9 node GEMMs in one launch, no serial dependency */
    dim3 gg(6, 2, 288);
    k_node_gemm_mma<<<gg, 256, GEMM_SMEM>>>(pZx, pOPT, pZall);

    /* fused epilogue */
    dim3 ge(8, 12, 32);
    k_epilogue<<<ge, 256>>>(x, pZall, mlpw, mlpb, out);
}

// round 14
// speedup vs baseline: 1.9554x; 1.9554x over previous
#include <cuda_runtime.h>
#include <cuda_fp16.h>
#include <cstdint>
#include <cstddef>

#define NBATCH 32
#define NNODE  512
#define NTIME  12
#define NCH    64
#define NM     (NTIME * NCH)            /* 768 */
#define NROWS  (NBATCH * NNODE * NTIME) /* 196608 */
#define ZELEMS ((size_t)NBATCH * NM * NNODE) /* 12582912 */
#define NN     ((size_t)NNODE * NNODE)

/* ------------------------------------------------------------------ */
/* Device scratch                                                      */
/* ------------------------------------------------------------------ */
__device__ float g_SW1[40 * 20];
__device__ float g_SW2[40 * 20];
__device__ float g_e1[NNODE * 20];
__device__ float g_e2[NNODE * 20];
__device__ float g_A[NNODE * NNODE];
__device__ float g_dinv[NNODE];
__device__ float g_Ls[NNODE * NNODE];
__device__ float g_T2[NNODE * NNODE];
__device__ float g_T3[NNODE * NNODE];
__device__ float g_P2[3][NNODE * NNODE];  /* S_s^2, fp32 */
__device__ float g_P3[3][NNODE * NNODE];  /* S_s^3, fp32 */
__device__ float g_Wid[64 * 64];

/* 9 transposed operators in fp16: op = s*3 + (p-1) */
__device__ __align__(1024) __half g_OPT[9][NNODE * NNODE];
__device__ __align__(1024) __half g_Zx[ZELEMS];
__device__ __align__(1024) __half g_Zall[9 * ZELEMS];
/* fp16 MLP weight blocks: [zi 0..8 = hop blocks][o][c]; [9] = Wid */
__device__ __align__(1024) __half g_Wh[10 * 64 * 64];

/* ------------------------------------------------------------------ */
/* PTX helpers (plain compute_100-legal)                               */
/* ------------------------------------------------------------------ */
__device__ __forceinline__ uint32_t smem_to_u32(const void* p) {
    uint32_t a;
    asm("{ .reg .u64 t; cvta.to.shared.u64 t, %1; cvt.u32.u64 %0, t; }"
        : "=r"(a) : "l"(p));
    return a;
}
__device__ __forceinline__ void cpasync16(uint32_t s, const void* g) {
    asm volatile("cp.async.cg.shared.global [%0], [%1], 16;" :: "r"(s), "l"(g));
}
#define CP_COMMIT() asm volatile("cp.async.commit_group;" ::: "memory")
#define CP_WAIT1()  asm volatile("cp.async.wait_group 1;" ::: "memory")
#define CP_WAIT0()  asm volatile("cp.async.wait_group 0;" ::: "memory")

__device__ __forceinline__ void ldsm4(uint32_t& r0, uint32_t& r1,
                                      uint32_t& r2, uint32_t& r3, uint32_t a) {
    asm volatile("ldmatrix.sync.aligned.m8n8.x4.shared.b16 {%0,%1,%2,%3}, [%4];"
                 : "=r"(r0), "=r"(r1), "=r"(r2), "=r"(r3) : "r"(a));
}
__device__ __forceinline__ void ldsm4t(uint32_t& r0, uint32_t& r1,
                                       uint32_t& r2, uint32_t& r3, uint32_t a) {
    asm volatile("ldmatrix.sync.aligned.m8n8.x4.trans.shared.b16 {%0,%1,%2,%3}, [%4];"
                 : "=r"(r0), "=r"(r1), "=r"(r2), "=r"(r3) : "r"(a));
}
__device__ __forceinline__ void mma16816f(float* c, const uint32_t* a,
                                          const uint32_t* b) {
    asm volatile(
        "mma.sync.aligned.m16n8k16.row.col.f32.f16.f16.f32 "
        "{%0,%1,%2,%3}, {%4,%5,%6,%7}, {%8,%9}, {%0,%1,%2,%3};"
        : "+f"(c[0]), "+f"(c[1]), "+f"(c[2]), "+f"(c[3])
        : "r"(a[0]), "r"(a[1]), "r"(a[2]), "r"(a[3]), "r"(b[0]), "r"(b[1]));
}

/* ------------------------------------------------------------------ */
/* Phase A (tiny)                                                      */
/* ------------------------------------------------------------------ */
__global__ void k_softmax(const float* __restrict__ W1,
                          const float* __restrict__ W2) {
    int j = threadIdx.x;
    if (j >= 40) return;
    const float* W = (j < 20) ? W1 : W2;
    float* S = (j < 20) ? g_SW1 : g_SW2;
    int col = (j < 20) ? j : (j - 20);
    float mx = -1e30f;
    for (int k = 0; k < 40; k++) mx = fmaxf(mx, W[k * 20 + col]);
    float s = 0.f;
    for (int k = 0; k < 40; k++) s += expf(W[k * 20 + col] - mx);
    float inv = 1.f / s;
    for (int k = 0; k < 40; k++) S[k * 20 + col] = expf(W[k * 20 + col] - mx) * inv;
}

__global__ void k_embed(const float* __restrict__ emb) {
    int row = blockIdx.x;
    int lane = threadIdx.x;
    float v1 = 0.f, v2 = 0.f;
    if (lane < 20) {
        for (int k = 0; k < 40; k++) {
            float e = emb[row * 40 + k];
            v1 += e * g_SW1[k * 20 + lane];
            v2 += e * g_SW2[k * 20 + lane];
        }
    }
    float n1 = v1 * v1, n2 = v2 * v2;
    for (int off = 16; off; off >>= 1) {
        n1 += __shfl_xor_sync(0xFFFFFFFFu, n1, off);
        n2 += __shfl_xor_sync(0xFFFFFFFFu, n2, off);
    }
    if (lane < 20) {
        g_e1[row * 20 + lane] = v1 / (sqrtf(n1) + 1e-8f);
        g_e2[row * 20 + lane] = v2 / (sqrtf(n2) + 1e-8f);
    }
}

__global__ void k_buildA(const float* __restrict__ adj) {
    int v = blockIdx.x;
    __shared__ float e1v[20];
    __shared__ float red[256];
    if (threadIdx.x < 20) e1v[threadIdx.x] = g_e1[v * 20 + threadIdx.x];
    __syncthreads();
    float sum = 0.f;
    for (int w = threadIdx.x; w < NNODE; w += 256) {
        float ad = adj[v * NNODE + w];
        float val = 9e-15f;
        if (ad > 0.f) {
            float dot = 0.f;
#pragma unroll
            for (int k = 0; k < 20; k++) dot += e1v[k] * g_e2[w * 20 + k];
            val = dot + ad;
        }
        g_A[v * NNODE + w] = val;
        sum += val;
    }
    red[threadIdx.x] = sum;
    __syncthreads();
    for (int s = 128; s; s >>= 1) {
        if (threadIdx.x < s) red[threadIdx.x] += red[threadIdx.x + s];
        __syncthreads();
    }
    if (threadIdx.x == 0) g_dinv[v] = 1.0f / sqrtf(red[0]);
}

__global__ void k_Ls() {
    int v = blockIdx.x;
    float dv = g_dinv[v];
    for (int w = threadIdx.x; w < NNODE; w += 256)
        g_Ls[v * NNODE + w] = -dv * g_A[v * NNODE + w] * g_dinv[w];
}

/* C = 2*A@B - (D ? D : I), 512x512 fp32 */
__global__ void k_gemm512(const float* __restrict__ A,
                          const float* __restrict__ B,
                          const float* __restrict__ D,
                          float* __restrict__ C) {
    __shared__ float As[16][68];
    __shared__ float Bs[16][68];
    const int tx = threadIdx.x, ty = threadIdx.y;
    const int t = ty * 16 + tx;
    const int i0 = blockIdx.y * 64, j0 = blockIdx.x * 64;
    float acc[4][4] = {};
    for (int k0 = 0; k0 < NNODE; k0 += 16) {
#pragma unroll
        for (int r = 0; r < 4; r++) {
            int idx = t + r * 256;
            int ia = idx >> 4, ka = idx & 15;
            As[ka][ia] = A[(size_t)(i0 + ia) * NNODE + k0 + ka];
            int kb = idx >> 6, jb = idx & 63;
            Bs[kb][jb] = B[(size_t)(k0 + kb) * NNODE + j0 + jb];
        }
        __syncthreads();
#pragma unroll
        for (int k = 0; k < 16; k++) {
            float av[4], bv[4];
#pragma unroll
            for (int i = 0; i < 4; i++) av[i] = As[k][ty * 4 + i];
#pragma unroll
            for (int j = 0; j < 4; j++) bv[j] = Bs[k][tx * 4 + j];
#pragma unroll
            for (int i = 0; i < 4; i++)
#pragma unroll
                for (int j = 0; j < 4; j++) acc[i][j] = fmaf(av[i], bv[j], acc[i][j]);
        }
        __syncthreads();
    }
#pragma unroll
    for (int i = 0; i < 4; i++)
#pragma unroll
        for (int j = 0; j < 4; j++) {
            int gi = i0 + ty * 4 + i, gj = j0 + tx * 4 + j;
            float sub = D ? D[(size_t)gi * NNODE + gj] : (gi == gj ? 1.f : 0.f);
            C[(size_t)gi * NNODE + gj] = 2.f * acc[i][j] - sub;
        }
}

/* Plain power GEMM, batched over 3 chains: mode 0: P2[s]=S_s@S_s,
   mode 1: P3[s]=S_s@P2[s]. */
__global__ void k_gemm512p(int mode, float* __restrict__ P2b,
                           float* __restrict__ P3b) {
    __shared__ float As[16][68];
    __shared__ float Bs[16][68];
    const int s = blockIdx.z;
    const float* S = (s == 0) ? g_Ls : (s == 1) ? g_T2 : g_T3;
    const float* A = S;
    const float* B = (mode == 0) ? S : (P2b + (size_t)s * NN);
    float* C = (mode == 0) ? (P2b + (size_t)s * NN) : (P3b + (size_t)s * NN);
    const int tx = threadIdx.x, ty = threadIdx.y;
    const int t = ty * 16 + tx;
    const int i0 = blockIdx.y * 64, j0 = blockIdx.x * 64;
    float acc[4][4] = {};
    for (int k0 = 0; k0 < NNODE; k0 += 16) {
#pragma unroll
        for (int r = 0; r < 4; r++) {
            int idx = t + r * 256;
            int ia = idx >> 4, ka = idx & 15;
            As[ka][ia] = A[(size_t)(i0 + ia) * NNODE + k0 + ka];
            int kb = idx >> 6, jb = idx & 63;
            Bs[kb][jb] = B[(size_t)(k0 + kb) * NNODE + j0 + jb];
        }
        __syncthreads();
#pragma unroll
        for (int k = 0; k < 16; k++) {
            float av[4], bv[4];
#pragma unroll
            for (int i = 0; i < 4; i++) av[i] = As[k][ty * 4 + i];
#pragma unroll
            for (int j = 0; j < 4; j++) bv[j] = Bs[k][tx * 4 + j];
#pragma unroll
            for (int i = 0; i < 4; i++)
#pragma unroll
                for (int j = 0; j < 4; j++) acc[i][j] = fmaf(av[i], bv[j], acc[i][j]);
        }
        __syncthreads();
    }
#pragma unroll
    for (int i = 0; i < 4; i++)
#pragma unroll
        for (int j = 0; j < 4; j++)
            C[(size_t)(i0 + ty * 4 + i) * NNODE + j0 + tx * 4 + j] = acc[i][j];
}

__global__ void k_wid(const float* __restrict__ mlpw) {
    int i = blockIdx.x * 256 + threadIdx.x;
    int o = i >> 6, c = i & 63;
    g_Wid[i] = mlpw[o * 832 + c] + mlpw[o * 832 + 64 + c] +
               mlpw[o * 832 + 128 + c] + mlpw[o * 832 + 192 + c];
}

/* fp16 weight blocks for tensor-core epilogue */
__global__ void k_wconv(const float* __restrict__ mlpw) {
    int i = blockIdx.x * 256 + threadIdx.x; /* < 40960 */
    int zi = i >> 12, j = i & 4095;
    int o = j >> 6, c = j & 63;
    float v;
    if (zi < 9) {
        int s = zi / 3, hop = zi % 3;
        v = mlpw[(size_t)o * 832 + (4 + 3 * s + hop) * 64 + c];
    } else {
        v = g_Wid[j];
    }
    g_Wh[zi * 4096 + j] = __float2half(v);
}

/* OPT[op][w][v] = (A_s^p)[v][w] fp16, op = s*3 + (p-1) */
__global__ void k_att9() {
    __shared__ float tile[32][33];
    const int op = blockIdx.z;
    const int s = op / 3, p = op % 3; /* p: 0->S, 1->S^2, 2->S^3 */
    const float* S;
    if (p == 0) S = (s == 0) ? g_Ls : (s == 1) ? g_T2 : g_T3;
    else if (p == 1) S = g_P2[s];
    else S = g_P3[s];
    __half* T = g_OPT[op];
    int w0 = blockIdx.x * 32, v0 = blockIdx.y * 32;
    int tx = threadIdx.x, ty = threadIdx.y;
#pragma unroll
    for (int i = 0; i < 4; i++)
        tile[ty + i * 8][tx] = S[(size_t)(v0 + ty + i * 8) * NNODE + w0 + tx];
    __syncthreads();
#pragma unroll
    for (int i = 0; i < 4; i++) {
        size_t idx = (size_t)(w0 + ty + i * 8) * NNODE + v0 + tx;
        T[idx] = __float2half(tile[tx][ty + i * 8]);
    }
}

/* Zx[b][m][v] = x[b][v][m], single fp16 */
__global__ void k_xpose(const float* __restrict__ x,
                        __half* __restrict__ Z) {
    __shared__ float tile[32][33];
    int m0 = blockIdx.x * 32, v0 = blockIdx.y * 32, b = blockIdx.z;
    int tx = threadIdx.x, ty = threadIdx.y;
#pragma unroll
    for (int i = 0; i < 4; i++)
        tile[ty + i * 8][tx] = x[((size_t)b * NNODE + v0 + ty + i * 8) * NM + m0 + tx];
    __syncthreads();
#pragma unroll
    for (int i = 0; i < 4; i++) {
        float val = tile[tx][ty + i * 8];
        size_t idx = ((size_t)b * NM + m0 + ty + i * 8) * NNODE + v0 + tx;
        Z[idx] = __float2half(val);
    }
}

/* ------------------------------------------------------------------ */
/* HMMA node GEMM (fp16): Zall[op] = Zx * OPT[op]   (R9-proven config) */
/* Block 128x128, 8 warps (2m x 4n) of 64x32, BK=16                    */
/* 3-stage cp.async ring, one __syncthreads per iteration              */
/* ------------------------------------------------------------------ */
#define BKQ 16
#define ROWB 48
#define MAT_BYTES (128 * ROWB)        /* 6144 */
#define STAGE_BYTES (2 * MAT_BYTES)   /* 12288 */
#define NSTAGE 3
#define GEMM_SMEM (NSTAGE * STAGE_BYTES) /* 36864 < 48KB */

__global__ void __launch_bounds__(256, 2) k_node_gemm_mma(
    const __half* __restrict__ Zx, const __half* __restrict__ OPTb,
    __half* __restrict__ Zallb) {
    extern __shared__ __align__(128) char smem[];
    const uint32_t sb = smem_to_u32(smem);
    const int tid = threadIdx.x, wid = tid >> 5, lane = tid & 31;
    const int m0 = blockIdx.x * 128;
    const int w0 = blockIdx.y * 128;
    const int op = blockIdx.z >> 5;
    const int b = blockIdx.z & 31;
    const __half* AT = OPTb + (size_t)op * NN;
    __half* Zout = Zallb + (size_t)op * ZELEMS;
    const size_t zbase = ((size_t)b * NM + m0) * NNODE;
    const int warp_m = wid & 1;
    const int warp_n = wid >> 1;

    float acc[4][4][4];
#pragma unroll
    for (int i = 0; i < 4; i++)
#pragma unroll
        for (int j = 0; j < 4; j++)
#pragma unroll
            for (int k = 0; k < 4; k++) acc[i][j][k] = 0.f;

    auto load_stage = [&](int it, int s) {
        const int k0 = it * BKQ;
        const uint32_t sbase = sb + s * STAGE_BYTES;
#pragma unroll
        for (int i = 0; i < 2; i++) {
            int c = tid + i * 256;
            int mat = c >> 8;
            int cm = c & 255;
            int row = cm >> 1;
            int h = cm & 1;
            uint32_t dst = sbase + mat * MAT_BYTES + row * ROWB + h * 16;
            const __half* src = (mat == 0)
                ? (Zx + zbase + (size_t)row * NNODE + k0 + h * 8)
                : (AT + (size_t)(w0 + row) * NNODE + k0 + h * 8);
            cpasync16(dst, src);
        }
    };

    load_stage(0, 0);
    CP_COMMIT();
    load_stage(1, 1);
    CP_COMMIT();

    const uint32_t lrow = lane & 15;
    const uint32_t lhalf = (uint32_t)(lane >> 4) * 16;
    const int NIT = NNODE / BKQ;

    for (int it = 0; it < NIT; it++) {
        if (it < NIT - 1) CP_WAIT1(); else CP_WAIT0();
        __syncthreads();
        if (it + 2 < NIT) {
            load_stage(it + 2, (it + 2) % NSTAGE);
            CP_COMMIT();
        }

        const uint32_t sbase = sb + (it % NSTAGE) * STAGE_BYTES;
        uint32_t z[4][4], bq[4][2];
#pragma unroll
        for (int mt = 0; mt < 4; mt++) {
            uint32_t a = sbase + (warp_m * 64 + mt * 16 + lrow) * ROWB + lhalf;
            ldsm4(z[mt][0], z[mt][1], z[mt][2], z[mt][3], a);
        }
#pragma unroll
        for (int nh = 0; nh < 2; nh++) {
            uint32_t a = sbase + MAT_BYTES +
                         (warp_n * 32 + nh * 16 + lrow) * ROWB + lhalf;
            uint32_t r0, r1, r2, r3;
            ldsm4(r0, r1, r2, r3, a);
            bq[nh * 2][0] = r0; bq[nh * 2][1] = r2;
            bq[nh * 2 + 1][0] = r1; bq[nh * 2 + 1][1] = r3;
        }
#pragma unroll
        for (int mt = 0; mt < 4; mt++)
#pragma unroll
            for (int nt = 0; nt < 4; nt++)
                mma16816f(acc[mt][nt], z[mt], bq[nt]);
    }

    const int qr = lane >> 2;
    const int qc = (lane & 3) * 2;
#pragma unroll
    for (int mt = 0; mt < 4; mt++) {
#pragma unroll
        for (int nt = 0; nt < 4; nt++) {
            const int row0 = m0 + warp_m * 64 + mt * 16 + qr;
            const int col = w0 + warp_n * 32 + nt * 8 + qc;
            const float* c = acc[mt][nt];
            size_t i0 = ((size_t)b * NM + row0) * NNODE + col;
            size_t i1 = i0 + (size_t)8 * NNODE;
            *(__half2*)(Zout + i0) = __floats2half2_rn(c[0], c[1]);
            *(__half2*)(Zout + i1) = __floats2half2_rn(c[2], c[3]);
        }
    }
}

/* ------------------------------------------------------------------ */
/* Tensor-core epilogue: per (b,t), OT[o][w] = sum_zi Wh[zi] @ Z_zi    */
/* A = Wh[zi] (64o x 64c, row-major, normal ldsm)                      */
/* B = Z tile (64c x 128w in smem) via ldmatrix.x4.trans              */
/* K = 10 x 64 (9 hop blocks + identity from Zx/Wid)                   */
/* Then smem transpose + bias + residual + relu, coalesced out write   */
/* ------------------------------------------------------------------ */
#define EP_WBLK 128
#define EP_ZPITCH_B 272                 /* 128 halves + 8 pad          */
#define EP_WPITCH_B 144                 /* 64 halves + 8 pad           */
#define EP_ZBYTES (64 * EP_ZPITCH_B)    /* 17408 */
#define EP_WBYTES (64 * EP_WPITCH_B)    /* 9216  */
#define EP_STAGE (EP_ZBYTES + EP_WBYTES)/* 26624 */
#define EP_SMEM (2 * EP_STAGE)          /* 53248 -> opt-in             */

__global__ void __launch_bounds__(256) k_epilogue_tc(
    const float* __restrict__ x, const __half* __restrict__ Zall,
    const __half* __restrict__ Zx, const __half* __restrict__ Wh,
    const float* __restrict__ bias, float* __restrict__ out) {
    extern __shared__ __align__(128) char smem[];
    const uint32_t sb = smem_to_u32(smem);
    const int tid = threadIdx.x, wid = tid >> 5, lane = tid & 31;
    const int w0 = blockIdx.x * EP_WBLK;
    const int t = blockIdx.y;
    const int b = blockIdx.z;

    float acc[4][2][4];
#pragma unroll
    for (int i = 0; i < 4; i++)
#pragma unroll
        for (int j = 0; j < 2; j++)
#pragma unroll
            for (int k = 0; k < 4; k++) acc[i][j][k] = 0.f;

    const size_t zrow0 = ((size_t)b * NM + t * 64) * NNODE + w0;

    auto load_stage = [&](int zi, int s) {
        const __half* Zsrc = (zi == 9) ? Zx : (Zall + (size_t)zi * ZELEMS);
        const uint32_t sZ = sb + s * EP_STAGE;
        const uint32_t sW = sZ + EP_ZBYTES;
#pragma unroll
        for (int i = 0; i < 4; i++) {          /* Z: 64 rows x 16 segs */
            int id = tid + i * 256;
            int c = id >> 4, seg = id & 15;
            cpasync16(sZ + c * EP_ZPITCH_B + seg * 16,
                      Zsrc + zrow0 + (size_t)c * NNODE + seg * 8);
        }
#pragma unroll
        for (int i = 0; i < 2; i++) {          /* W: 64 rows x 8 segs  */
            int id = tid + i * 256;
            int o = id >> 3, seg = id & 7;
            cpasync16(sW + o * EP_WPITCH_B + seg * 16,
                      Wh + zi * 4096 + o * 64 + seg * 8);
        }
    };

    load_stage(0, 0);
    CP_COMMIT();
    load_stage(1, 1);
    CP_COMMIT();

    /* B trans-load address: lane groups of 8 -> (c-half, w-half)      */
    const int lg = lane >> 3;                  /* 0..3 */
    const int lr = lane & 7;
    const int crow_off = (lg & 1) * 8 + lr;    /* row within 16-c step */
    const int wcol = wid * 16 + (lg >> 1) * 8; /* warp's 16-w strip    */

    for (int zi = 0; zi < 10; zi++) {
        if (zi < 9) CP_WAIT1(); else CP_WAIT0();
        __syncthreads();

        const uint32_t sZ = sb + (zi & 1) * EP_STAGE;
        const uint32_t sW = sZ + EP_ZBYTES;
#pragma unroll
        for (int ks = 0; ks < 4; ks++) {
            const int c0 = ks * 16;
            uint32_t a[4][4];
#pragma unroll
            for (int mt = 0; mt < 4; mt++) {
                uint32_t ad = sW + (mt * 16 + (lane & 15)) * EP_WPITCH_B +
                              c0 * 2 + (lane >> 4) * 16;
                ldsm4(a[mt][0], a[mt][1], a[mt][2], a[mt][3], ad);
            }
            uint32_t bq[2][2];
            {
                uint32_t bd = sZ + (c0 + crow_off) * EP_ZPITCH_B + wcol * 2;
                uint32_t r0, r1, r2, r3;
                ldsm4t(r0, r1, r2, r3, bd);
                bq[0][0] = r0; bq[0][1] = r1;   /* w 0-7  */
                bq[1][0] = r2; bq[1][1] = r3;   /* w 8-15 */
            }
#pragma unroll
            for (int mt = 0; mt < 4; mt++) {
                mma16816f(acc[mt][0], a[mt], bq[0]);
                mma16816f(acc[mt][1], a[mt], bq[1]);
            }
        }
        __syncthreads();
        if (zi + 2 < 10) {
            load_stage(zi + 2, zi & 1);
            CP_COMMIT();
        }
    }

    /* transpose through smem: Obuf[w][o], pitch 68 floats */
    float* Obuf = (float*)smem;
    const int qr = lane >> 2;
    const int qc = (lane & 3) * 2;
#pragma unroll
    for (int mt = 0; mt < 4; mt++)
#pragma unroll
        for (int nb = 0; nb < 2; nb++) {
            const int o0 = mt * 16 + qr;
            const int wl = wid * 16 + nb * 8 + qc;
            const float* c = acc[mt][nb];
            Obuf[(size_t)wl * 68 + o0] = c[0];
            Obuf[(size_t)(wl + 1) * 68 + o0] = c[1];
            Obuf[(size_t)wl * 68 + o0 + 8] = c[2];
            Obuf[(size_t)(wl + 1) * 68 + o0 + 8] = c[3];
        }
    __syncthreads();

    /* coalesced final write: bias + residual + relu */
#pragma unroll
    for (int i = 0; i < 8; i++) {
        int j = tid + i * 256;                 /* 0..2047 */
        int w = j >> 4, oq = (j & 15) * 4;
        size_t r = ((size_t)(b * NNODE + w0 + w) * NTIME + t);
        const float4 bb = *(const float4*)(bias + oq);
        const float4 xo = *(const float4*)(x + r * 64 + oq);
        float* ob = Obuf + (size_t)w * 68 + oq;
        float4 v;
        v.x = fmaxf(ob[0] + bb.x + xo.x, 0.f);
        v.y = fmaxf(ob[1] + bb.y + xo.y, 0.f);
        v.z = fmaxf(ob[2] + bb.z + xo.z, 0.f);
        v.w = fmaxf(ob[3] + bb.w + xo.w, 0.f);
        *(float4*)(out + r * 64 + oq) = v;
    }
}

/* ------------------------------------------------------------------ */
extern "C" void kernel_launch(void* const* d_in, const int* in_sizes, int n_in,
                              void* d_out, int out_size) {
    (void)in_sizes; (void)n_in; (void)out_size;
    const float* x    = (const float*)d_in[0];
    const float* adj  = (const float*)d_in[1];
    const float* emb  = (const float*)d_in[2];
    const float* W1   = (const float*)d_in[3];
    const float* W2   = (const float*)d_in[4];
    const float* mlpw = (const float*)d_in[5];
    const float* mlpb = (const float*)d_in[6];
    float* out = (float*)d_out;

    float *pLs, *pT2, *pT3, *pP2, *pP3;
    __half *pOPT, *pZx, *pZall, *pWh;
    cudaGetSymbolAddress((void**)&pLs, g_Ls);
    cudaGetSymbolAddress((void**)&pT2, g_T2);
    cudaGetSymbolAddress((void**)&pT3, g_T3);
    cudaGetSymbolAddress((void**)&pP2, g_P2);
    cudaGetSymbolAddress((void**)&pP3, g_P3);
    cudaGetSymbolAddress((void**)&pOPT, g_OPT);
    cudaGetSymbolAddress((void**)&pZx, g_Zx);
    cudaGetSymbolAddress((void**)&pZall, g_Zall);
    cudaGetSymbolAddress((void**)&pWh, g_Wh);

    cudaFuncSetAttribute(k_epilogue_tc,
                         cudaFuncAttributeMaxDynamicSharedMemorySize, EP_SMEM);

    /* Phase A: supports + powers */
    k_softmax<<<1, 64>>>(W1, W2);
    k_embed<<<512, 32>>>(emb);
    k_buildA<<<512, 256>>>(adj);
    k_Ls<<<512, 256>>>();
    dim3 g512(8, 8), b512(16, 16);
    k_gemm512<<<g512, b512>>>(pLs, pLs, (const float*)nullptr, pT2);
    k_gemm512<<<g512, b512>>>(pLs, pT2, pLs, pT3);
    dim3 gp(8, 8, 3);
    k_gemm512p<<<gp, b512>>>(0, pP2, pP3);
    k_gemm512p<<<gp, b512>>>(1, pP2, pP3);
    dim3 ga9(16, 16, 9), bat(32, 8);
    k_att9<<<ga9, bat>>>();
    k_wid<<<16, 256>>>(mlpw);
    k_wconv<<<160, 256>>>(mlpw);

    /* transpose x -> Zx (fp16, rounded ONCE) */
    dim3 gx(24, 16, 32), bx(32, 8);
    k_xpose<<<gx, bx>>>(x, pZx);

    /* all 9 node GEMMs in one launch (R9-proven config) */
    dim3 gg(6, 4, 288);
    k_node_gemm_mma<<<gg, 256, GEMM_SMEM>>>(pZx, pOPT, pZall);

    /* tensor-core epilogue */
    dim3 ge(4, 12, 32);
    k_epilogue_tc<<<ge, 256, EP_SMEM>>>(x, pZall, pZx, pWh, mlpb, out);
}